// round 1
// baseline (speedup 1.0000x reference)
#include <cuda_runtime.h>
#include <cstdint>

// Problem constants (fixed by the reference: N,H,W,K,F,D = 16,512,512,1,9976,12)
#define NB   16
#define HB   512
#define WB   512
#define DB   12
#define HWC  (HB * WB)          // 262144 = 2^18
#define PC   (NB * HWC)         // 4,194,304 pixels
#define HW_SHIFT 18
#define HW_MASK  (HWC - 1)

// Flag: 1 if pix_to_face buffer is int64, 0 if int32. Written by detect kernel.
__device__ int g_idx64;

// Decide int32 vs int64 layout of pix_to_face by inspecting the first 512
// 8-byte pairs. For genuine int64 data (values in {-1} ∪ [0, 159616)), every
// pair (lo, hi) satisfies (hi==0 && lo>=0) || (hi==-1 && lo==-1). For int32
// data the "hi" slots are independent random face indices and violate this
// with overwhelming probability.
__global__ void detect_kernel(const int* __restrict__ p) {
    int i = threadIdx.x * 2;             // 512 threads -> 1024 ints = 512 pairs
    int lo = p[i];
    int hi = p[i + 1];
    bool good = (hi == 0 && lo >= 0) || (hi == -1 && lo == -1);
    int allgood = __syncthreads_and(good ? 1 : 0);
    if (threadIdx.x == 0) g_idx64 = allgood;
}

__global__ __launch_bounds__(256) void interp_kernel(
    const int*    __restrict__ p2f,   // int32 view (int64 handled via stride-2)
    const float*  __restrict__ bary,  // [P,3]
    const float4* __restrict__ attr,  // [N*F, 9] float4  == [N*F,3,12] float
    float*        __restrict__ out)   // [N,13,H,W]
{
    const int pid = blockIdx.x * 256 + threadIdx.x;

    const int is64 = g_idx64;  // uniform, L2-hot
    // For int64 input, the value lives in the low 32-bit word (little-endian);
    // -1 sign-extends so the low word is still -1.
    int face = is64 ? __ldcs(p2f + 2 * (size_t)pid)
                    : __ldcs(p2f + (size_t)pid);

    const float* bp = bary + (size_t)pid * 3;
    float b0 = __ldcs(bp + 0);
    float b1 = __ldcs(bp + 1);
    float b2 = __ldcs(bp + 2);

    float vis = 1.0f;
    if (face < 0) {            // background pixel: result is exactly 0
        face = 0;              // (clamped gather, matching the reference)
        b0 = b1 = b2 = 0.0f;
        vis = 0.0f;
    }

    // Gather the 3 corners x 12 attrs = 9 aligned float4 loads (MLP=9).
    const float4* ap = attr + (size_t)face * 9;
    float4 c0 = __ldg(ap + 0), c1 = __ldg(ap + 1), c2 = __ldg(ap + 2); // corner 0
    float4 d0 = __ldg(ap + 3), d1 = __ldg(ap + 4), d2 = __ldg(ap + 5); // corner 1
    float4 e0 = __ldg(ap + 6), e1 = __ldg(ap + 7), e2 = __ldg(ap + 8); // corner 2

    float r[12];
    r[0]  = fmaf(b0, c0.x, fmaf(b1, d0.x, b2 * e0.x));
    r[1]  = fmaf(b0, c0.y, fmaf(b1, d0.y, b2 * e0.y));
    r[2]  = fmaf(b0, c0.z, fmaf(b1, d0.z, b2 * e0.z));
    r[3]  = fmaf(b0, c0.w, fmaf(b1, d0.w, b2 * e0.w));
    r[4]  = fmaf(b0, c1.x, fmaf(b1, d1.x, b2 * e1.x));
    r[5]  = fmaf(b0, c1.y, fmaf(b1, d1.y, b2 * e1.y));
    r[6]  = fmaf(b0, c1.z, fmaf(b1, d1.z, b2 * e1.z));
    r[7]  = fmaf(b0, c1.w, fmaf(b1, d1.w, b2 * e1.w));
    r[8]  = fmaf(b0, c2.x, fmaf(b1, d2.x, b2 * e2.x));
    r[9]  = fmaf(b0, c2.y, fmaf(b1, d2.y, b2 * e2.y));
    r[10] = fmaf(b0, c2.z, fmaf(b1, d2.z, b2 * e2.z));
    r[11] = fmaf(b0, c2.w, fmaf(b1, d2.w, b2 * e2.w));

    const int n  = pid >> HW_SHIFT;
    const int hw = pid & HW_MASK;
    float* obase = out + (size_t)n * 13 * HWC + hw;

    // 13 channel stores, each warp-coalesced (consecutive hw across lanes).
    // Streaming hint: output is write-once, keep it out of L2's way.
#pragma unroll
    for (int d = 0; d < 12; d++)
        __stcs(obase + (size_t)d * HWC, r[d]);
    __stcs(obase + (size_t)12 * HWC, vis);
}

extern "C" void kernel_launch(void* const* d_in, const int* in_sizes, int n_in,
                              void* d_out, int out_size) {
    const int*    p2f  = (const int*)d_in[0];
    const float*  bary = (const float*)d_in[1];
    const float4* attr = (const float4*)d_in[2];
    float*        out  = (float*)d_out;

    detect_kernel<<<1, 512>>>(p2f);
    interp_kernel<<<PC / 256, 256>>>(p2f, bary, attr, out);
}

// round 2
// speedup vs baseline: 1.3571x; 1.3571x over previous
#include <cuda_runtime.h>
#include <cuda_fp16.h>
#include <cstdint>

// Problem constants (fixed by the reference: N,H,W,K,F,D = 16,512,512,1,9976,12)
#define NB   16
#define HB   512
#define WB   512
#define DB   12
#define FACES (NB * 9976)        // 159616 global faces
#define HWC  (HB * WB)           // 262144 = 2^18
#define PC   (NB * HWC)          // 4,194,304 pixels
#define HW_SHIFT 18
#define HW_MASK  (HWC - 1)

// fp16-repacked attributes: per face 36 halves + 4 zero-pad = 40 halves = 80 B
// = 5 x 16B chunks, 16B-aligned. 159616 * 80 B = 12.77 MB static scratch.
__device__ float4 g_attrh[FACES * 5];

// Flag: 1 if pix_to_face buffer is int64, 0 if int32.
__device__ int g_idx64;

__global__ void detect_kernel(const int* __restrict__ p) {
    int i = threadIdx.x * 2;             // 512 threads -> 512 (lo,hi) pairs
    int lo = p[i];
    int hi = p[i + 1];
    bool good = (hi == 0 && lo >= 0) || (hi == -1 && lo == -1);
    int allgood = __syncthreads_and(good ? 1 : 0);
    if (threadIdx.x == 0) g_idx64 = allgood;
}

// Repack fp32 attrs [FACES,36] -> fp16 [FACES,40] (pad with zeros).
// One thread per output 32-bit word (half2). Coalesced on both sides.
__global__ __launch_bounds__(256) void repack_kernel(const float* __restrict__ a) {
    int wid = blockIdx.x * 256 + threadIdx.x;          // [0, FACES*20)
    if (wid >= FACES * 20) return;
    int face = wid / 20;
    int w    = wid - face * 20;
    int a0   = 2 * w;
    __half2 h;
    if (a0 < 36) {
        float x = a[(size_t)face * 36 + a0];
        float y = a[(size_t)face * 36 + a0 + 1];
        h = __floats2half2_rn(x, y);
    } else {
        h = __floats2half2_rn(0.0f, 0.0f);
    }
    reinterpret_cast<__half2*>(g_attrh)[wid] = h;
}

// Main kernel: block = 256 threads = 256 pixels.
// Phase 1: stage face indices.
// Phase 2: cooperative gather — 1280 16B chunks, consecutive lanes on
//          consecutive chunks (80B contiguous per pixel) -> ~16 sectors per
//          LDG.128 instead of 32 scattered lines.
// Phase 3: per-thread interpolation from smem (stride 21 words, odd ->
//          conflict-free LDS.32), planar coalesced stores.
__global__ __launch_bounds__(256) void interp_kernel(
    const int*   __restrict__ p2f,
    const float* __restrict__ bary,
    float*       __restrict__ out)
{
    __shared__ int      s_face[256];
    __shared__ unsigned s_attr[256 * 21];   // 21504 B

    const int tid  = threadIdx.x;
    const int pid  = blockIdx.x * 256 + tid;
    const int is64 = g_idx64;

    // int64 little-endian: value lives in the low word; -1 sign-extends.
    int rawface = is64 ? __ldcs(p2f + 2 * (size_t)pid)
                       : __ldcs(p2f + (size_t)pid);
    s_face[tid] = rawface;
    __syncthreads();

    const float4* ah = g_attrh;
#pragma unroll
    for (int i = 0; i < 5; i++) {
        int chunk = i * 256 + tid;          // [0, 1280)
        int p = chunk / 5;
        int c = chunk - p * 5;
        int f = s_face[p];
        f = f < 0 ? 0 : f;
        float4 v = __ldg(ah + (size_t)f * 5 + c);
        unsigned* dst = s_attr + p * 21 + c * 4;
        dst[0] = __float_as_uint(v.x);
        dst[1] = __float_as_uint(v.y);
        dst[2] = __float_as_uint(v.z);
        dst[3] = __float_as_uint(v.w);
    }
    __syncthreads();

    const float* bp = bary + (size_t)pid * 3;
    float b0 = __ldcs(bp + 0);
    float b1 = __ldcs(bp + 1);
    float b2 = __ldcs(bp + 2);

    float vis = 1.0f;
    if (rawface < 0) {                      // background: exact zeros
        b0 = b1 = b2 = 0.0f;
        vis = 0.0f;
    }

    float r[12];
#pragma unroll
    for (int d = 0; d < 12; d++) r[d] = 0.0f;

    const unsigned* src = s_attr + tid * 21;
#pragma unroll
    for (int w = 0; w < 18; w++) {          // word w = attrs (2w, 2w+1)
        __half2 h = *reinterpret_cast<const __half2*>(src + w);
        float2 f2 = __half22float2(h);
        const int k  = w / 6;               // corner 0..2 (12 attrs = 6 words)
        const int d0 = (w - k * 6) * 2;
        const float bk = (k == 0) ? b0 : ((k == 1) ? b1 : b2);
        r[d0]     = fmaf(bk, f2.x, r[d0]);
        r[d0 + 1] = fmaf(bk, f2.y, r[d0 + 1]);
    }

    const int n  = pid >> HW_SHIFT;
    const int hw = pid & HW_MASK;
    float* obase = out + (size_t)n * 13 * HWC + hw;
#pragma unroll
    for (int d = 0; d < 12; d++)
        __stcs(obase + (size_t)d * HWC, r[d]);
    __stcs(obase + (size_t)12 * HWC, vis);
}

extern "C" void kernel_launch(void* const* d_in, const int* in_sizes, int n_in,
                              void* d_out, int out_size) {
    const int*   p2f  = (const int*)d_in[0];
    const float* bary = (const float*)d_in[1];
    const float* attr = (const float*)d_in[2];
    float*       out  = (float*)d_out;

    detect_kernel<<<1, 512>>>(p2f);
    repack_kernel<<<(FACES * 20 + 255) / 256, 256>>>(attr);
    interp_kernel<<<PC / 256, 256>>>(p2f, bary, out);
}